// round 17
// baseline (speedup 1.0000x reference)
#include <cuda_runtime.h>

// Problem constants: B=4, M=8, N=128, D=32, 2D=64, H=64. BM = B*M = 32 sets.
#define NSET 32
#define NN   128
#define DD   32
#define DD2  64

// Padded strides: 17 float4 = 272 B row stride => 4-bank skew, conflict-free.
#define A1S_STRIDE4 17
#define DS_STRIDE   68

// Scratch (device globals -- no allocation allowed)
__device__ float g_x1[NSET * NN * DD];
__device__ float g_A1[NSET * NN * DD2];
__device__ float g_A2[NSET * NN * DD2];
__device__ float g_mask[NSET * NN];
__device__ int   g_nv[NSET];               // valid prefix length per set

__device__ __forceinline__ float tanh_ap(float x) {
    float r; asm("tanh.approx.f32 %0,%1;" : "=f"(r) : "f"(x)); return r;
}

// scalar gelu (jax tanh form) via tanh.approx.
__device__ __forceinline__ float gelu_f(float t) {
    float u  = t * t;
    float z  = t * fmaf(0.0356774081f, u, 0.7978845608f);
    float th = tanh_ap(z);
    float ht = 0.5f * t;
    return fmaf(th, ht, ht);
}

// Scalar nonlinear gelu-dot contribution: acc += (hv*t)*tanh(z(t)), t = a+d.
// Linear part 0.5*Sum(v*t) factored out as P[i]+Q[j].
__device__ __forceinline__ void gelu_nl_s(float a, float d, float hv, float& acc) {
    float t = a + d;
    float u = t * t;
    float z = t * fmaf(0.0356774081f, u, 0.7978845608f);
    float w = hv * t;
    acc = fmaf(tanh_ap(z), w, acc);
}

// ---------------------------------------------------------------------------
// Kernel 1: per-set norm stats + set_norm + MLP1 + A1/A2 precompute + Nv.
// grid = NSET * 8 blocks (one set x 16 rows each), 256 threads.
// GEMM phases register-blocked 1x4 with LDS.128 weight loads.
// ---------------------------------------------------------------------------
__global__ __launch_bounds__(256) void k1(
    const float* __restrict__ x, const float* __restrict__ x_size,
    const float* __restrict__ W1a, const float* __restrict__ b1a,
    const float* __restrict__ W1b, const float* __restrict__ b1b,
    const float* __restrict__ W2a)
{
    __shared__ float xs[NN * DD];           // staging; later hb (1024) + x1b (512)
    __shared__ float w1a[DD * DD2];
    __shared__ float w1b[DD2 * DD];
    __shared__ float w2a[DD * DD2];
    __shared__ float xn[16 * DD];
    __shared__ float maskS[NN];
    __shared__ float red[8];
    __shared__ float statS[2];

    const int bm   = blockIdx.x >> 3;
    const int tile = blockIdx.x & 7;
    const int r0   = tile * 16;
    const int tid  = threadIdx.x;

    const float4* xg  = (const float4*)(x + bm * (NN * DD));
    float4*       xs4 = (float4*)xs;
    float lsum = 0.f;
    #pragma unroll
    for (int i = tid; i < 1024; i += 256) {
        float4 v = xg[i];
        xs4[i] = v;
        lsum += v.x + v.y + v.z + v.w;
    }
    #pragma unroll
    for (int i = tid; i < 512; i += 256) ((float4*)w1a)[i] = ((const float4*)W1a)[i];
    #pragma unroll
    for (int i = tid; i < 512; i += 256) ((float4*)w1b)[i] = ((const float4*)W1b)[i];
    #pragma unroll
    for (int i = tid; i < 512; i += 256) ((float4*)w2a)[i] = ((const float4*)W2a)[i];
    __syncthreads();

    if (tid < NN) {
        const float4* row4 = (const float4*)(xs + tid * DD);
        bool nz = false;
        #pragma unroll
        for (int e = 0; e < 8; e++) {
            float4 v = row4[e];
            nz = nz || (v.x != 0.f) || (v.y != 0.f) || (v.z != 0.f) || (v.w != 0.f);
        }
        maskS[tid] = nz ? 1.f : 0.f;
    }
    #pragma unroll
    for (int o = 16; o; o >>= 1) lsum += __shfl_xor_sync(0xffffffffu, lsum, o);
    if ((tid & 31) == 0) red[tid >> 5] = lsum;
    __syncthreads();
    const float denom = x_size[bm >> 3] * (float)DD;
    if (tid == 0) {
        float s = 0.f;
        #pragma unroll
        for (int w = 0; w < 8; w++) s += red[w];
        statS[0] = s / denom;
    }
    if (tid < 32) {
        int mx = -1;
        #pragma unroll
        for (int c = 0; c < 4; c++) {
            unsigned bal = __ballot_sync(0xffffffffu, maskS[c * 32 + tid] != 0.f);
            if (bal) { int hi = 31 - __clz((int)bal); if (c * 32 + hi > mx) mx = c * 32 + hi; }
        }
        if (tid == 0) g_nv[bm] = mx + 1;
    }
    __syncthreads();
    const float mean = statS[0];

    float lss = 0.f;
    #pragma unroll
    for (int i = tid; i < 1024; i += 256) {
        float4 v = xs4[i];
        float m = maskS[i >> 3];
        float a = v.x - mean, b = v.y - mean, c = v.z - mean, d = v.w - mean;
        lss += (a * a + b * b + c * c + d * d) * m;
    }
    #pragma unroll
    for (int o = 16; o; o >>= 1) lss += __shfl_xor_sync(0xffffffffu, lss, o);
    if ((tid & 31) == 0) red[tid >> 5] = lss;
    __syncthreads();
    if (tid == 0) {
        float s = 0.f;
        #pragma unroll
        for (int w = 0; w < 8; w++) s += red[w];
        statS[1] = 1.0f / (sqrtf(s / denom) + 1e-8f);
    }
    __syncthreads();
    const float inv = statS[1];

    #pragma unroll
    for (int i = tid; i < 512; i += 256) {
        int n = r0 + (i >> 5);
        int e = i & 31;
        xn[i] = (xs[n * DD + e] - mean) * inv * maskS[n];
    }
    if (tid < 16) g_mask[bm * NN + r0 + tid] = maskS[r0 + tid];
    __syncthreads();

    float* hb  = xs;          // 16*64
    float* x1b = xs + 1024;   // 16*32
    const int n  = tid >> 4;      // 0..15 (local row)
    const int kq = tid & 15;      // quad index

    {
        const float4* w1a4 = (const float4*)w1a;
        float4 acc = ((const float4*)b1a)[kq];
        const float* xr = xn + n * DD;
        #pragma unroll
        for (int e = 0; e < DD; e++) {
            float xv  = xr[e];
            float4 w  = w1a4[e * 16 + kq];
            acc.x = fmaf(xv, w.x, acc.x);
            acc.y = fmaf(xv, w.y, acc.y);
            acc.z = fmaf(xv, w.z, acc.z);
            acc.w = fmaf(xv, w.w, acc.w);
        }
        float4 g;
        g.x = gelu_f(acc.x); g.y = gelu_f(acc.y);
        g.z = gelu_f(acc.z); g.w = gelu_f(acc.w);
        ((float4*)hb)[n * 16 + kq] = g;
    }
    __syncthreads();

    {
        const float2* w1b2 = (const float2*)w1b;
        float2 acc = ((const float2*)b1b)[kq];
        const float* hr = hb + n * DD2;
        #pragma unroll
        for (int k = 0; k < DD2; k++) {
            float h  = hr[k];
            float2 w = w1b2[k * 16 + kq];
            acc.x = fmaf(h, w.x, acc.x);
            acc.y = fmaf(h, w.y, acc.y);
        }
        float m = maskS[r0 + n];
        acc.x *= m; acc.y *= m;
        ((float2*)x1b)[n * 16 + kq] = acc;
        *(float2*)(g_x1 + bm * (NN * DD) + (r0 + n) * DD + kq * 2) = acc;
    }
    __syncthreads();

    {
        const float4* w2a4 = (const float4*)w2a;
        float4 a1 = make_float4(0.f, 0.f, 0.f, 0.f);
        float4 a2 = make_float4(0.f, 0.f, 0.f, 0.f);
        const float* x1r = x1b + n * DD;
        const float* xnr = xn  + n * DD;
        #pragma unroll
        for (int e = 0; e < DD; e++) {
            float xa = x1r[e];
            float xb = xnr[e];
            float4 w = w2a4[e * 16 + kq];
            a1.x = fmaf(xa, w.x, a1.x); a1.y = fmaf(xa, w.y, a1.y);
            a1.z = fmaf(xa, w.z, a1.z); a1.w = fmaf(xa, w.w, a1.w);
            a2.x = fmaf(xb, w.x, a2.x); a2.y = fmaf(xb, w.y, a2.y);
            a2.z = fmaf(xb, w.z, a2.z); a2.w = fmaf(xb, w.w, a2.w);
        }
        const int go = bm * (NN * DD2) + (r0 + n) * DD2 + kq * 4;
        *(float4*)(g_A1 + go) = a1;
        *(float4*)(g_A2 + go) = a2;
    }
}

// ---------------------------------------------------------------------------
// Kernel 2: pair scores (SCALAR math A/B) + re-tiled aggregation.
// grid = NSET * 8 (one set x 16 j's), 512 threads, 2 CTAs/SM.
// Thread owns j = tid&15 and up to 4 i's (bi + 32r).
// ---------------------------------------------------------------------------
__global__ __launch_bounds__(512, 2) void k2(
    const float* __restrict__ x,
    const float* __restrict__ b2a, const float* __restrict__ W2b,
    const float* __restrict__ b2b, const float* __restrict__ w3,
    const float* __restrict__ b3, float* __restrict__ out)
{
    __shared__ float A1s[NN * A1S_STRIDE4 * 4];   // padded rows; reused as x1s later
    __shared__ float dS[16 * DS_STRIDE];
    __shared__ float vS[DD2];
    __shared__ float sS[NN * 16];
    __shared__ float PS[NN];
    __shared__ float QS[16];
    __shared__ float4 part4[512];                 // aggregation partials (8 KB)
    __shared__ float cS;

    const int bm = blockIdx.x >> 3;
    const int jt = blockIdx.x & 7;
    const int j0 = jt * 16;
    const int tid = threadIdx.x;

    const int Nv = g_nv[bm];
    if (j0 >= Nv) {
        if (tid < 128) {
            float4 z4 = make_float4(0.f, 0.f, 0.f, 0.f);
            ((float4*)(out + bm * (NN * DD) + j0 * DD))[tid] = z4;
        }
        return;
    }
    const int nr   = min(4, max(2, (Nv + 31) >> 5));
    const int aggN = nr * 32;

    // --- stage A1 (padded rows), dS, half-v, c ---
    const float4* a1g  = (const float4*)(g_A1 + bm * (NN * DD2));
    float4*       A1s4 = (float4*)A1s;
    #pragma unroll
    for (int idx = tid; idx < 2048; idx += 512) {
        int i  = idx >> 4;
        int k4 = idx & 15;
        A1s4[i * A1S_STRIDE4 + k4] = a1g[idx];
    }
    #pragma unroll
    for (int i = tid; i < 1024; i += 512) {
        int jj = i >> 6, k = i & 63;
        dS[jj * DS_STRIDE + k] = b2a[k] - g_A2[bm * (NN * DD2) + (j0 + jj) * DD2 + k];
    }
    if (tid >= 448) {
        int kk = tid - 448;
        float acc = 0.f;
        #pragma unroll
        for (int h = 0; h < 64; h++) acc = fmaf(W2b[kk * 64 + h], w3[h], acc);
        vS[kk] = 0.5f * acc;
    }
    if (tid == 0) {
        float acc = 0.f;
        #pragma unroll
        for (int h = 0; h < 64; h++) acc = fmaf(b2b[h], w3[h], acc);
        cS = acc;
    }
    __syncthreads();

    // --- P[i] and Q[j]; vS holds 0.5*v ---
    if (tid < NN) {
        const float* row = A1s + tid * (A1S_STRIDE4 * 4);
        float acc = 0.f;
        #pragma unroll
        for (int k = 0; k < DD2; k++) acc = fmaf(row[k], vS[k], acc);
        PS[tid] = acc;
    } else if (tid < NN + 16) {
        int jj = tid - NN;
        const float* row = dS + jj * DS_STRIDE;
        float acc = 0.f;
        #pragma unroll
        for (int k = 0; k < DD2; k++) acc = fmaf(row[k], vS[k], acc);
        QS[jj] = acc;
    }
    __syncthreads();

    // --- pair phase (scalar): thread owns j = tid&15 and up to 4 i's ---
    const int j  = tid & 15;
    const int bi = tid >> 4;     // 0..31
    const float4* dj4 = (const float4*)(dS + j * DS_STRIDE);
    const float4* vv4 = (const float4*)vS;

    float ac0 = 0.f, ac1 = 0.f, ac2 = 0.f, ac3 = 0.f;
    const bool g2 = (nr >= 3), g3 = (nr >= 4);
    #pragma unroll
    for (int k4 = 0; k4 < 16; k4++) {
        float4 dd = dj4[k4];
        float4 hv = vv4[k4];
        float4 q;
        q = A1s4[(bi      ) * A1S_STRIDE4 + k4];
        gelu_nl_s(q.x, dd.x, hv.x, ac0);
        gelu_nl_s(q.y, dd.y, hv.y, ac0);
        gelu_nl_s(q.z, dd.z, hv.z, ac0);
        gelu_nl_s(q.w, dd.w, hv.w, ac0);
        q = A1s4[(bi + 32) * A1S_STRIDE4 + k4];
        gelu_nl_s(q.x, dd.x, hv.x, ac1);
        gelu_nl_s(q.y, dd.y, hv.y, ac1);
        gelu_nl_s(q.z, dd.z, hv.z, ac1);
        gelu_nl_s(q.w, dd.w, hv.w, ac1);
        if (g2) {
            q = A1s4[(bi + 64) * A1S_STRIDE4 + k4];
            gelu_nl_s(q.x, dd.x, hv.x, ac2);
            gelu_nl_s(q.y, dd.y, hv.y, ac2);
            gelu_nl_s(q.z, dd.z, hv.z, ac2);
            gelu_nl_s(q.w, dd.w, hv.w, ac2);
        }
        if (g3) {
            q = A1s4[(bi + 96) * A1S_STRIDE4 + k4];
            gelu_nl_s(q.x, dd.x, hv.x, ac3);
            gelu_nl_s(q.y, dd.y, hv.y, ac3);
            gelu_nl_s(q.z, dd.z, hv.z, ac3);
            gelu_nl_s(q.w, dd.w, hv.w, ac3);
        }
    }
    {
        const float base = cS + QS[j];
        sS[(bi      ) * 16 + j] = base + PS[bi      ] + ac0;
        sS[(bi + 32) * 16 + j] = base + PS[bi + 32] + ac1;
        if (g2) sS[(bi + 64) * 16 + j] = base + PS[bi + 64] + ac2;
        if (g3) sS[(bi + 96) * 16 + j] = base + PS[bi + 96] + ac3;
    }
    __syncthreads();

    // --- stage x1 into smem (reuse A1s region; pair phase done) ---
    float* x1s = A1s;
    {
        const float4* x1g4 = (const float4*)(g_x1 + bm * (NN * DD));
        #pragma unroll
        for (int idx = tid; idx < 1024; idx += 512) ((float4*)x1s)[idx] = x1g4[idx];
    }
    __syncthreads();

    // --- aggregation, re-tiled: thread = (iq, jj, d4).
    // iq = tid>>7 (0..3): i in [iq*32, iq*32+32); jj = (tid>>3)&15; d4 = tid&7.
    // float4 x1 loads -> LDS per output / 4 vs old layout. ---
    {
        const int iq = tid >> 7;
        const int jj = (tid >> 3) & 15;
        const int d4 = tid & 7;
        float4 acc = make_float4(0.f, 0.f, 0.f, 0.f);
        if (iq * 32 < aggN) {
            const float* sp = sS + jj;
            const float4* xp = (const float4*)x1s + d4;
            const int ib = iq * 32;
            #pragma unroll 8
            for (int i = ib; i < ib + 32; i++) {
                float s   = sp[i * 16];
                float4 xv = xp[i * 8];
                acc.x = fmaf(s, xv.x, acc.x);
                acc.y = fmaf(s, xv.y, acc.y);
                acc.z = fmaf(s, xv.z, acc.z);
                acc.w = fmaf(s, xv.w, acc.w);
            }
        }
        part4[tid] = acc;
    }
    __syncthreads();
    if (tid < 128) {
        const int jj = tid >> 3;
        const int d4 = tid & 7;
        float4 a = part4[tid];
        float4 b = part4[tid + 128];
        float4 c = part4[tid + 256];
        float4 e = part4[tid + 384];
        const int gj = j0 + jj;
        const float m  = g_mask[bm * NN + gj];
        const float bb = b3[0];
        const int gidx = bm * (NN * DD) + gj * DD + d4 * 4;
        float4 xv = *(const float4*)(x + gidx);
        float4 o;
        o.x = (a.x + b.x + c.x + e.x + bb + xv.x) * m;
        o.y = (a.y + b.y + c.y + e.y + bb + xv.y) * m;
        o.z = (a.z + b.z + c.z + e.z + bb + xv.z) * m;
        o.w = (a.w + b.w + c.w + e.w + bb + xv.w) * m;
        *(float4*)(out + gidx) = o;
    }
}

// ---------------------------------------------------------------------------
extern "C" void kernel_launch(void* const* d_in, const int* in_sizes, int n_in,
                              void* d_out, int out_size)
{
    (void)in_sizes; (void)n_in; (void)out_size;
    const float* x    = (const float*)d_in[0];
    const float* xsz  = (const float*)d_in[1];
    const float* W1a  = (const float*)d_in[2];
    const float* b1a  = (const float*)d_in[3];
    const float* W1b  = (const float*)d_in[4];
    const float* b1b  = (const float*)d_in[5];
    const float* W2a  = (const float*)d_in[6];
    const float* b2a  = (const float*)d_in[7];
    const float* W2b  = (const float*)d_in[8];
    const float* b2b  = (const float*)d_in[9];
    const float* w3   = (const float*)d_in[10];
    const float* b3   = (const float*)d_in[11];
    float* out = (float*)d_out;

    k1<<<NSET * 8, 256>>>(x, xsz, W1a, b1a, W1b, b1b, W2a);
    k2<<<NSET * 8, 512>>>(x, b2a, W2b, b2b, w3, b3, out);
}